// round 2
// baseline (speedup 1.0000x reference)
#include <cuda_runtime.h>

#define EPS 1e-9f
#define MAX_NODES 200000

// Per-node (x, y) table: 1.6 MB, lives in L2 after the node kernel writes it.
__device__ float2 g_xy[MAX_NODES];
// [0] = proximity sum, [1] = compactness sum (fp64 accumulators)
__device__ double g_acc[2];

__global__ void init_kernel() {
    g_acc[0] = 0.0;
    g_acc[1] = 0.0;
}

__device__ __forceinline__ double block_reduce_add(double v) {
    __shared__ double s[32];
    int lane = threadIdx.x & 31;
    int wid  = threadIdx.x >> 5;
#pragma unroll
    for (int o = 16; o > 0; o >>= 1) v += __shfl_down_sync(0xffffffffu, v, o);
    if (lane == 0) s[wid] = v;
    __syncthreads();
    int nw = (blockDim.x + 31) >> 5;
    v = (threadIdx.x < nw) ? s[threadIdx.x] : 0.0;
    if (wid == 0) {
#pragma unroll
        for (int o = 16; o > 0; o >>= 1) v += __shfl_down_sync(0xffffffffu, v, o);
    }
    return v;
}

// Extract (x, y) per node, store packed table, and compute compactness term:
// quad(p, origin) = (1 - aa) / safe(aa) with aa = 1 - x^2 - y^2.
__global__ void node_kernel(const float* __restrict__ z, int n) {
    int i = blockIdx.x * blockDim.x + threadIdx.x;
    double local = 0.0;
    if (i < n) {
        float2 xy = *reinterpret_cast<const float2*>(z + (size_t)i * 128);
        g_xy[i] = xy;
        float aa   = 1.0f - (xy.x * xy.x + xy.y * xy.y);
        float num  = 1.0f - aa;
        float safe = copysignf(fmaxf(fabsf(aa), EPS), aa);
        local = (double)(num / safe);
    }
    double bs = block_reduce_add(local);
    if (threadIdx.x == 0) atomicAdd(&g_acc[1], bs);
}

// Per-edge numerator and clamped denominator of the quadrance.
__device__ __forceinline__ void edge_nd(float2 a, float2 b, float& num, float& safe) {
    float aa = 1.0f - (a.x * a.x + a.y * a.y);
    float bb = 1.0f - (b.x * b.x + b.y * b.y);
    float ab = 1.0f - (a.x * b.x + a.y * b.y);
    float p  = aa * bb;
    num  = ab * ab - p;
    safe = copysignf(fmaxf(fabsf(p), EPS), p);
}

// 4 edges per thread: vectorized int4 index loads, 8 L2 gathers (MLP=8), and
// Montgomery batch inversion (one fp32 division serves 4 edges -> 4x fewer MUFU.RCP).
__global__ void edge_kernel(const int* __restrict__ src, const int* __restrict__ dst,
                            int ngroups) {
    const float2* __restrict__ xy = g_xy;  // read-only path for the gathers
    int t = blockIdx.x * blockDim.x + threadIdx.x;
    double local = 0.0;
    if (t < ngroups) {
        int4 s = reinterpret_cast<const int4*>(src)[t];
        int4 d = reinterpret_cast<const int4*>(dst)[t];
        float2 a0 = __ldg(&xy[s.x]), b0 = __ldg(&xy[d.x]);
        float2 a1 = __ldg(&xy[s.y]), b1 = __ldg(&xy[d.y]);
        float2 a2 = __ldg(&xy[s.z]), b2 = __ldg(&xy[d.z]);
        float2 a3 = __ldg(&xy[s.w]), b3 = __ldg(&xy[d.w]);

        float n0, n1, n2, n3, d0, d1, d2, d3;
        edge_nd(a0, b0, n0, d0);
        edge_nd(a1, b1, n1, d1);
        edge_nd(a2, b2, n2, d2);
        edge_nd(a3, b3, n3, d3);

        // Batch inversion: |d_i| >= EPS=1e-9 so the 4-way product (>=1e-36)
        // stays normal in fp32; products of large |aa|~O(10) stay << fp32 max.
        float t01   = d0 * d1;
        float t012  = t01 * d2;
        float t0123 = t012 * d3;
        float r     = 1.0f / t0123;
        float inv3  = r * t012;
        float r012  = r * d3;
        float inv2  = r012 * t01;
        float r01   = r012 * d2;
        float inv1  = r01 * d0;
        float inv0  = r01 * d1;

        local = (double)(n0 * inv0) + (double)(n1 * inv1)
              + (double)(n2 * inv2) + (double)(n3 * inv3);
    }
    double bs = block_reduce_add(local);
    if (threadIdx.x == 0) atomicAdd(&g_acc[0], bs);
}

// Single-warp finalize: tail edges (if E % 4 != 0), spread over first
// min(10, E) edges on the lines l = cross([x,y,1],[0,0,1]) = (y,-x,0),
// then combine all three loss terms.
__global__ void finalize_kernel(const int* __restrict__ src, const int* __restrict__ dst,
                                float* __restrict__ out, int n_edges, int n_nodes,
                                int tail_start) {
    int lane = threadIdx.x;

    double tailsum = 0.0;
    for (int e = tail_start + lane; e < n_edges; e += 32) {
        float2 a = g_xy[src[e]], b = g_xy[dst[e]];
        float num, safe;
        edge_nd(a, b, num, safe);
        tailsum += (double)(num / safe);
    }

    int nsp = n_edges < 10 ? n_edges : 10;
    double sp = 0.0;
    if (lane < nsp) {
        float2 a = g_xy[src[lane]], b = g_xy[dst[lane]];
        // lines: la = (a.y, -a.x, 0) -> inner(la,lb) = -(x_a x_b + y_a y_b), etc.
        float laa = -(a.x * a.x + a.y * a.y);
        float lbb = -(b.x * b.x + b.y * b.y);
        float lab = -(a.x * b.x + a.y * b.y);
        float p   = laa * lbb;
        float num = lab * lab - p;
        float safe = copysignf(fmaxf(fabsf(p), EPS), p);
        sp = (double)(num / safe);
    }

#pragma unroll
    for (int o = 16; o > 0; o >>= 1) {
        tailsum += __shfl_down_sync(0xffffffffu, tailsum, o);
        sp      += __shfl_down_sync(0xffffffffu, sp, o);
    }

    if (lane == 0) {
        double prox   = (g_acc[0] + tailsum) / (double)n_edges;
        double comp   = g_acc[1] / (double)n_nodes;
        double spread = (nsp > 0) ? (sp / (double)nsp) : 0.0;
        out[0] = (float)(prox + comp + 0.1 * spread);
    }
}

extern "C" void kernel_launch(void* const* d_in, const int* in_sizes, int n_in,
                              void* d_out, int out_size) {
    const float* z  = (const float*)d_in[0];
    const int*   ei = (const int*)d_in[1];
    int n_nodes = in_sizes[0] / 128;
    int n_edges = in_sizes[1] / 2;
    const int* src = ei;
    const int* dst = ei + n_edges;

    init_kernel<<<1, 1>>>();
    node_kernel<<<(n_nodes + 255) / 256, 256>>>(z, n_nodes);

    int ngroups = n_edges / 4;
    if (ngroups > 0)
        edge_kernel<<<(ngroups + 255) / 256, 256>>>(src, dst, ngroups);

    finalize_kernel<<<1, 32>>>(src, dst, (float*)d_out, n_edges, n_nodes, ngroups * 4);
}